// round 8
// baseline (speedup 1.0000x reference)
#include <cuda_runtime.h>
#include <cstdint>
#include <cfloat>

#define NN 50000
#define FIN 512
#define H1C 64     // 8 heads * 8
#define H2C 40     // 1 head * 40
#define EMAX 1700000

// ---------------- scratch (device globals; no allocation allowed) -------------
__device__ int   g_tsrc[EMAX + NN];   // decoded src (original order)
__device__ int   g_tdst[EMAX + NN];   // decoded dst (original order)
__device__ int   g_esrc[EMAX + NN];   // src sorted by dst (CSR payload)
__device__ int   g_deg[NN];           // in-degree histogram
__device__ int   g_rowp[NN + 1];      // CSR row pointers
__device__ int   g_pos[NN];           // scatter cursors
__device__ float g_h1[NN * H1C];      // x @ W1
__device__ float g_as1[NN * 8];       // a_src layer1
__device__ float g_ad1[NN * 8];       // a_dst layer1
__device__ float g_out1[NN * H1C];    // relu(agg1 + b1)
__device__ float g_h2[NN * H2C];      // out1 @ W2
__device__ float g_as2[NN];
__device__ float g_ad2[NN];

__device__ __forceinline__ float lrelu_exp(float e) {
    e = (e < 0.f) ? 0.2f * e : e;
    return __expf(e);
}

// ---------------- CSR build ----------------------------------------------------
__global__ void k_zdeg() {
    int i = blockIdx.x * blockDim.x + threadIdx.x;
    if (i < NN) g_deg[i] = 0;
}

// decode edge index (int32 OR int64 little-endian) + self loops + histogram
__global__ void k_decode(const int* __restrict__ w, int E) {
    bool is64 = (w[1] == 0 && w[3] == 0 && w[5] == 0 && w[7] == 0);
    int i = blockIdx.x * blockDim.x + threadIdx.x;
    int ET = E + NN;
    if (i >= ET) return;
    int s, d;
    if (i >= E) { s = d = i - E; }
    else if (is64) {
        const long long* e64 = (const long long*)w;
        s = (int)e64[i]; d = (int)e64[E + i];
    } else {
        s = w[i]; d = w[E + i];
    }
    g_tsrc[i] = s;
    g_tdst[i] = d;
    atomicAdd(&g_deg[d], 1);
}

// single-block exclusive scan of g_deg -> g_rowp, g_pos
__global__ void k_scan(int ET) {
    __shared__ int sh[1024];
    int t = threadIdx.x;
    const int CH = (NN + 1023) / 1024;     // 49
    int b = t * CH;
    int e = b + CH; if (e > NN) e = NN; if (b > NN) b = NN;
    int s = 0;
    for (int i = b; i < e; i++) s += g_deg[i];
    sh[t] = s;
    __syncthreads();
    for (int off = 1; off < 1024; off <<= 1) {
        int v = (t >= off) ? sh[t - off] : 0;
        __syncthreads();
        sh[t] += v;
        __syncthreads();
    }
    int run = sh[t] - s;                   // exclusive prefix
    for (int i = b; i < e; i++) {
        int d = g_deg[i];
        g_rowp[i] = run;
        g_pos[i]  = run;
        run += d;
    }
    if (t == 1023) g_rowp[NN] = ET;
}

__global__ void k_scatter(int ET) {
    int i = blockIdx.x * blockDim.x + threadIdx.x;
    if (i >= ET) return;
    int s = g_tsrc[i], d = g_tdst[i];
    int p = atomicAdd(&g_pos[d], 1);
    g_esrc[p] = s;
}

// ---------------- GEMM1: h1 = x[50000,512] @ W1[512,64] + fused a1 ------------
// BM=64, BN=64, BK=16, 256 threads, 4x4 per thread
__global__ void k_gemm1(const float* __restrict__ x, const float* __restrict__ W,
                        const float* __restrict__ attS, const float* __restrict__ attD) {
    __shared__ float As[16][64];   // [k][m]
    __shared__ float Bs[16][64];   // [k][n]
    int t = threadIdx.x;
    int m0 = blockIdx.x * 64;
    int tx = t & 15, ty = t >> 4;
    int lrow = t >> 2, lq = t & 3;   // A-load: row, quarter
    int krow = t >> 4, kq = t & 15;  // B-load: k-row, quarter
    float acc[4][4] = {};
    for (int k0 = 0; k0 < FIN; k0 += 16) {
        float4 av = make_float4(0.f, 0.f, 0.f, 0.f);
        int gm = m0 + lrow;
        if (gm < NN) av = *(const float4*)(x + (size_t)gm * FIN + k0 + 4 * lq);
        As[4 * lq + 0][lrow] = av.x;
        As[4 * lq + 1][lrow] = av.y;
        As[4 * lq + 2][lrow] = av.z;
        As[4 * lq + 3][lrow] = av.w;
        *(float4*)&Bs[krow][4 * kq] = *(const float4*)(W + (size_t)(k0 + krow) * 64 + 4 * kq);
        __syncthreads();
#pragma unroll
        for (int k = 0; k < 16; k++) {
            float4 a = *(const float4*)&As[k][ty * 4];
            float4 b = *(const float4*)&Bs[k][tx * 4];
            acc[0][0] += a.x * b.x; acc[0][1] += a.x * b.y; acc[0][2] += a.x * b.z; acc[0][3] += a.x * b.w;
            acc[1][0] += a.y * b.x; acc[1][1] += a.y * b.y; acc[1][2] += a.y * b.z; acc[1][3] += a.y * b.w;
            acc[2][0] += a.z * b.x; acc[2][1] += a.z * b.y; acc[2][2] += a.z * b.z; acc[2][3] += a.z * b.w;
            acc[3][0] += a.w * b.x; acc[3][1] += a.w * b.y; acc[3][2] += a.w * b.z; acc[3][3] += a.w * b.w;
        }
        __syncthreads();
    }
    // attention-vector partials for this thread's 4 columns
    float aS[4], aD[4];
#pragma unroll
    for (int j = 0; j < 4; j++) {
        aS[j] = __ldg(attS + tx * 4 + j);
        aD[j] = __ldg(attD + tx * 4 + j);
    }
#pragma unroll
    for (int i = 0; i < 4; i++) {
        int gm = m0 + ty * 4 + i;
        float sp = acc[i][0] * aS[0] + acc[i][1] * aS[1] + acc[i][2] * aS[2] + acc[i][3] * aS[3];
        float dp = acc[i][0] * aD[0] + acc[i][1] * aD[1] + acc[i][2] * aD[2] + acc[i][3] * aD[3];
        sp += __shfl_xor_sync(0xffffffffu, sp, 1);
        dp += __shfl_xor_sync(0xffffffffu, dp, 1);
        if (gm < NN) {
            float4 v = make_float4(acc[i][0], acc[i][1], acc[i][2], acc[i][3]);
            *(float4*)(g_h1 + (size_t)gm * 64 + tx * 4) = v;
            if (!(tx & 1)) {
                g_as1[gm * 8 + (tx >> 1)] = sp;
                g_ad1[gm * 8 + (tx >> 1)] = dp;
            }
        }
    }
}

// ---------------- layer1 segmented aggregation (warp per dst node) -------------
// pass1: softmax denominators per head; pass2: alpha-weighted sum of h1[src].
// Fused: + b1, relu, single store. No atomics.
__global__ void k_agg1(const float* __restrict__ b1) {
    int n = (blockIdx.x * blockDim.x + threadIdx.x) >> 5;
    int lane = threadIdx.x & 31;
    if (n >= NN) return;
    int beg = g_rowp[n], end = g_rowp[n + 1];

    float4 adx = *(const float4*)(g_ad1 + n * 8);
    float4 ady = *(const float4*)(g_ad1 + n * 8 + 4);
    float ad[8] = {adx.x, adx.y, adx.z, adx.w, ady.x, ady.y, ady.z, ady.w};

    // pass 1: per-head denominators (warp-strided)
    float den[8] = {};
    for (int j = beg + lane; j < end; j += 32) {
        int s = g_esrc[j];
        float4 a0 = *(const float4*)(g_as1 + s * 8);
        float4 a1 = *(const float4*)(g_as1 + s * 8 + 4);
        den[0] += lrelu_exp(a0.x + ad[0]); den[1] += lrelu_exp(a0.y + ad[1]);
        den[2] += lrelu_exp(a0.z + ad[2]); den[3] += lrelu_exp(a0.w + ad[3]);
        den[4] += lrelu_exp(a1.x + ad[4]); den[5] += lrelu_exp(a1.y + ad[5]);
        den[6] += lrelu_exp(a1.z + ad[6]); den[7] += lrelu_exp(a1.w + ad[7]);
    }
#pragma unroll
    for (int h = 0; h < 8; h++) {
#pragma unroll
        for (int o = 16; o > 0; o >>= 1)
            den[h] += __shfl_xor_sync(0xffffffffu, den[h], o);
    }

    // pass 2: lane handles columns 2*lane, 2*lane+1 (head = lane>>2)
    int h = lane >> 2;
    float myden = den[h] + 1e-16f;
    float myad  = ad[h];
    float acc0 = 0.f, acc1 = 0.f;
    for (int j = beg; j < end; j++) {
        int s = g_esrc[j];                          // broadcast load
        float ex = lrelu_exp(g_as1[s * 8 + h] + myad);
        float al = ex / myden;
        float2 hv = *(const float2*)(g_h1 + (size_t)s * 64 + 2 * lane);
        acc0 += al * hv.x;
        acc1 += al * hv.y;
    }
    float2 o;
    o.x = fmaxf(acc0 + __ldg(b1 + 2 * lane), 0.f);
    o.y = fmaxf(acc1 + __ldg(b1 + 2 * lane + 1), 0.f);
    *(float2*)(g_out1 + (size_t)n * 64 + 2 * lane) = o;
}

// ---------------- layer2 node phase: out1 @ W2, a2 ----------------------------
__global__ void k_l2(const float* __restrict__ W2,
                     const float* __restrict__ aS2, const float* __restrict__ aD2) {
    __shared__ float Wsm[64 * 40];
    __shared__ float aSs[40], aDs[40];
    int t = threadIdx.x;
    for (int i = t; i < 64 * 40; i += 128) Wsm[i] = W2[i];
    if (t < 40) { aSs[t] = aS2[t]; aDs[t] = aD2[t]; }
    __syncthreads();
    int n = blockIdx.x * 128 + t;
    if (n >= NN) return;
    float acc[40] = {};
    const float* r = g_out1 + (size_t)n * 64;
#pragma unroll
    for (int k4 = 0; k4 < 16; k4++) {
        float4 v = *(const float4*)(r + k4 * 4);
#pragma unroll
        for (int c = 0; c < 40; c++) {
            acc[c] += v.x * Wsm[(4 * k4 + 0) * 40 + c]
                    + v.y * Wsm[(4 * k4 + 1) * 40 + c]
                    + v.z * Wsm[(4 * k4 + 2) * 40 + c]
                    + v.w * Wsm[(4 * k4 + 3) * 40 + c];
        }
    }
    float s2 = 0.f, d2 = 0.f;
#pragma unroll
    for (int c = 0; c < 40; c++) {
        g_h2[(size_t)n * 40 + c] = acc[c];
        s2 += acc[c] * aSs[c];
        d2 += acc[c] * aDs[c];
    }
    g_as2[n] = s2;
    g_ad2[n] = d2;
}

// ---------------- layer2 segmented aggregation + bias + log_softmax -----------
__global__ void k_agg2(const float* __restrict__ b2, float* __restrict__ out) {
    int n = (blockIdx.x * blockDim.x + threadIdx.x) >> 5;
    int lane = threadIdx.x & 31;
    if (n >= NN) return;
    int beg = g_rowp[n], end = g_rowp[n + 1];
    float myad = g_ad2[n];

    // pass 1: denominator
    float den = 0.f;
    for (int j = beg + lane; j < end; j += 32)
        den += lrelu_exp(g_as2[g_esrc[j]] + myad);
#pragma unroll
    for (int o = 16; o > 0; o >>= 1)
        den += __shfl_xor_sync(0xffffffffu, den, o);
    den += 1e-16f;

    // pass 2: lanes 0..19 accumulate columns 2*lane, 2*lane+1
    float acc0 = 0.f, acc1 = 0.f;
    for (int j = beg; j < end; j++) {
        int s = g_esrc[j];                          // broadcast
        float al = lrelu_exp(g_as2[s] + myad) / den;
        if (lane < 20) {
            float2 hv = *(const float2*)(g_h2 + (size_t)s * 40 + 2 * lane);
            acc0 += al * hv.x;
            acc1 += al * hv.y;
        }
    }

    // fused bias + log_softmax over 40 columns
    float v0 = -FLT_MAX, v1 = -FLT_MAX;
    if (lane < 20) {
        v0 = acc0 + __ldg(b2 + 2 * lane);
        v1 = acc1 + __ldg(b2 + 2 * lane + 1);
    }
    float m = fmaxf(v0, v1);
#pragma unroll
    for (int o = 16; o > 0; o >>= 1)
        m = fmaxf(m, __shfl_xor_sync(0xffffffffu, m, o));
    float sum = (lane < 20) ? (__expf(v0 - m) + __expf(v1 - m)) : 0.f;
#pragma unroll
    for (int o = 16; o > 0; o >>= 1)
        sum += __shfl_xor_sync(0xffffffffu, sum, o);
    float ls = m + logf(sum);
    if (lane < 20) {
        float2 o2; o2.x = v0 - ls; o2.y = v1 - ls;
        *(float2*)(out + (size_t)n * 40 + 2 * lane) = o2;
    }
}

// ------------------------------------------------------------------------------
extern "C" void kernel_launch(void* const* d_in, const int* in_sizes, int n_in,
                              void* d_out, int out_size) {
    const float* x     = (const float*)d_in[0];
    const int*   ei    = (const int*)d_in[1];
    const float* W1    = (const float*)d_in[2];
    const float* attS1 = (const float*)d_in[3];
    const float* attD1 = (const float*)d_in[4];
    const float* b1    = (const float*)d_in[5];
    const float* W2    = (const float*)d_in[6];
    const float* attS2 = (const float*)d_in[7];
    const float* attD2 = (const float*)d_in[8];
    const float* b2    = (const float*)d_in[9];
    float* out = (float*)d_out;
    (void)b1;

    int E = in_sizes[1] / 2;
    if (E > EMAX) E = EMAX;
    int ET = E + NN;

    k_zdeg<<<(NN + 255) / 256, 256>>>();
    k_decode<<<(ET + 255) / 256, 256>>>(ei, E);
    k_scan<<<1, 1024>>>(ET);
    k_scatter<<<(ET + 255) / 256, 256>>>(ET);
    k_gemm1<<<(NN + 63) / 64, 256>>>(x, W1, attS1, attD1);
    k_agg1<<<(NN * 32 + 255) / 256, 256>>>(b1);
    k_l2<<<(NN + 127) / 128, 128>>>(W2, attS2, attD2);
    k_agg2<<<(NN * 32 + 255) / 256, 256>>>(b2, out);
}

// round 9
// speedup vs baseline: 1.4728x; 1.4728x over previous
#include <cuda_runtime.h>
#include <cstdint>
#include <cfloat>

#define NN 50000
#define FIN 512
#define H1C 64     // 8 heads * 8
#define H2C 40     // 1 head * 40
#define EMAX 1700000

// ---------------- scratch (device globals; no allocation allowed) -------------
__device__ int   g_tsrc[EMAX + NN];   // decoded src (original order)
__device__ int   g_tdst[EMAX + NN];   // decoded dst (original order)
__device__ int   g_esrc[EMAX + NN];   // src sorted by dst (CSR payload)
__device__ int   g_deg[NN];           // in-degree histogram
__device__ int   g_rowp[NN + 1];      // CSR row pointers
__device__ int   g_pos[NN];           // scatter cursors
__device__ float g_h1[NN * H1C];      // x @ W1
__device__ float g_as1[NN * 8];       // a_src layer1
__device__ float g_ad1[NN * 8];       // a_dst layer1
__device__ float g_out1[NN * H1C];    // relu(agg1 + b1)
__device__ float g_h2[NN * H2C];      // out1 @ W2
__device__ float g_as2[NN];
__device__ float g_ad2[NN];

__device__ __forceinline__ float lrelu_exp(float e) {
    e = (e < 0.f) ? 0.2f * e : e;
    return __expf(e);
}

// ---------------- CSR build ----------------------------------------------------
__global__ void k_zdeg() {
    int i = blockIdx.x * blockDim.x + threadIdx.x;
    if (i < NN) g_deg[i] = 0;
}

// decode edge index (int32 OR int64 little-endian) + self loops + histogram
__global__ void k_decode(const int* __restrict__ w, int E) {
    bool is64 = (w[1] == 0 && w[3] == 0 && w[5] == 0 && w[7] == 0);
    int i = blockIdx.x * blockDim.x + threadIdx.x;
    int ET = E + NN;
    if (i >= ET) return;
    int s, d;
    if (i >= E) { s = d = i - E; }
    else if (is64) {
        const long long* e64 = (const long long*)w;
        s = (int)e64[i]; d = (int)e64[E + i];
    } else {
        s = w[i]; d = w[E + i];
    }
    g_tsrc[i] = s;
    g_tdst[i] = d;
    atomicAdd(&g_deg[d], 1);
}

// single-block exclusive scan of g_deg -> g_rowp, g_pos
__global__ void k_scan(int ET) {
    __shared__ int sh[1024];
    int t = threadIdx.x;
    const int CH = (NN + 1023) / 1024;     // 49
    int b = t * CH;
    int e = b + CH; if (e > NN) e = NN; if (b > NN) b = NN;
    int s = 0;
    for (int i = b; i < e; i++) s += g_deg[i];
    sh[t] = s;
    __syncthreads();
    for (int off = 1; off < 1024; off <<= 1) {
        int v = (t >= off) ? sh[t - off] : 0;
        __syncthreads();
        sh[t] += v;
        __syncthreads();
    }
    int run = sh[t] - s;                   // exclusive prefix
    for (int i = b; i < e; i++) {
        int d = g_deg[i];
        g_rowp[i] = run;
        g_pos[i]  = run;
        run += d;
    }
    if (t == 1023) g_rowp[NN] = ET;
}

__global__ void k_scatter(int ET) {
    int i = blockIdx.x * blockDim.x + threadIdx.x;
    if (i >= ET) return;
    int s = g_tsrc[i], d = g_tdst[i];
    int p = atomicAdd(&g_pos[d], 1);
    g_esrc[p] = s;
}

// ---------------- GEMM1: h1 = x[50000,512] @ W1[512,64] + fused a1 ------------
// BM=64, BN=64, BK=16, 256 threads, 4x4 per thread
__global__ void k_gemm1(const float* __restrict__ x, const float* __restrict__ W,
                        const float* __restrict__ attS, const float* __restrict__ attD) {
    __shared__ float As[16][64];   // [k][m]
    __shared__ float Bs[16][64];   // [k][n]
    int t = threadIdx.x;
    int m0 = blockIdx.x * 64;
    int tx = t & 15, ty = t >> 4;
    int lrow = t >> 2, lq = t & 3;   // A-load: row, quarter
    int krow = t >> 4, kq = t & 15;  // B-load: k-row, quarter
    float acc[4][4] = {};
    for (int k0 = 0; k0 < FIN; k0 += 16) {
        float4 av = make_float4(0.f, 0.f, 0.f, 0.f);
        int gm = m0 + lrow;
        if (gm < NN) av = *(const float4*)(x + (size_t)gm * FIN + k0 + 4 * lq);
        As[4 * lq + 0][lrow] = av.x;
        As[4 * lq + 1][lrow] = av.y;
        As[4 * lq + 2][lrow] = av.z;
        As[4 * lq + 3][lrow] = av.w;
        *(float4*)&Bs[krow][4 * kq] = *(const float4*)(W + (size_t)(k0 + krow) * 64 + 4 * kq);
        __syncthreads();
#pragma unroll
        for (int k = 0; k < 16; k++) {
            float4 a = *(const float4*)&As[k][ty * 4];
            float4 b = *(const float4*)&Bs[k][tx * 4];
            acc[0][0] += a.x * b.x; acc[0][1] += a.x * b.y; acc[0][2] += a.x * b.z; acc[0][3] += a.x * b.w;
            acc[1][0] += a.y * b.x; acc[1][1] += a.y * b.y; acc[1][2] += a.y * b.z; acc[1][3] += a.y * b.w;
            acc[2][0] += a.z * b.x; acc[2][1] += a.z * b.y; acc[2][2] += a.z * b.z; acc[2][3] += a.z * b.w;
            acc[3][0] += a.w * b.x; acc[3][1] += a.w * b.y; acc[3][2] += a.w * b.z; acc[3][3] += a.w * b.w;
        }
        __syncthreads();
    }
    // attention-vector partials for this thread's 4 columns
    float aS[4], aD[4];
#pragma unroll
    for (int j = 0; j < 4; j++) {
        aS[j] = __ldg(attS + tx * 4 + j);
        aD[j] = __ldg(attD + tx * 4 + j);
    }
#pragma unroll
    for (int i = 0; i < 4; i++) {
        int gm = m0 + ty * 4 + i;
        float sp = acc[i][0] * aS[0] + acc[i][1] * aS[1] + acc[i][2] * aS[2] + acc[i][3] * aS[3];
        float dp = acc[i][0] * aD[0] + acc[i][1] * aD[1] + acc[i][2] * aD[2] + acc[i][3] * aD[3];
        sp += __shfl_xor_sync(0xffffffffu, sp, 1);
        dp += __shfl_xor_sync(0xffffffffu, dp, 1);
        if (gm < NN) {
            float4 v = make_float4(acc[i][0], acc[i][1], acc[i][2], acc[i][3]);
            *(float4*)(g_h1 + (size_t)gm * 64 + tx * 4) = v;
            if (!(tx & 1)) {
                g_as1[gm * 8 + (tx >> 1)] = sp;
                g_ad1[gm * 8 + (tx >> 1)] = dp;
            }
        }
    }
}

// ---------------- layer1 aggregation: SINGLE PASS, warp per dst node ----------
// lane = (edge-group eg 0..3) x (col-group c 0..7); col-group c == head c.
// Accumulate S[c] = sum_j ex_j * h1[s_j, 8c..8c+7] and den[c] = sum_j ex_j,
// then out = S/den (softmax division factored out of the sum).
__global__ void k_agg1(const float* __restrict__ b1) {
    int n = (blockIdx.x * blockDim.x + threadIdx.x) >> 5;
    int lane = threadIdx.x & 31;
    if (n >= NN) return;
    int eg = lane >> 3;       // 0..3
    int c  = lane & 7;        // col group == head
    int beg = g_rowp[n], end = g_rowp[n + 1];

    float myad = g_ad1[n * 8 + c];
    float den = 0.f;
    float4 acc0 = make_float4(0.f, 0.f, 0.f, 0.f);
    float4 acc1 = make_float4(0.f, 0.f, 0.f, 0.f);

    for (int j = beg + eg; j < end; j += 4) {
        int s = g_esrc[j];
        float ex = lrelu_exp(g_as1[s * 8 + c] + myad);
        const float* hr = g_h1 + (size_t)s * 64 + c * 8;
        float4 h0 = *(const float4*)(hr);
        float4 h1v = *(const float4*)(hr + 4);
        den += ex;
        acc0.x += ex * h0.x;  acc0.y += ex * h0.y;  acc0.z += ex * h0.z;  acc0.w += ex * h0.w;
        acc1.x += ex * h1v.x; acc1.y += ex * h1v.y; acc1.z += ex * h1v.z; acc1.w += ex * h1v.w;
    }

    // combine 4 edge groups (lanes differing in bits 3,4)
#pragma unroll
    for (int o = 8; o <= 16; o <<= 1) {
        den    += __shfl_xor_sync(0xffffffffu, den, o);
        acc0.x += __shfl_xor_sync(0xffffffffu, acc0.x, o);
        acc0.y += __shfl_xor_sync(0xffffffffu, acc0.y, o);
        acc0.z += __shfl_xor_sync(0xffffffffu, acc0.z, o);
        acc0.w += __shfl_xor_sync(0xffffffffu, acc0.w, o);
        acc1.x += __shfl_xor_sync(0xffffffffu, acc1.x, o);
        acc1.y += __shfl_xor_sync(0xffffffffu, acc1.y, o);
        acc1.z += __shfl_xor_sync(0xffffffffu, acc1.z, o);
        acc1.w += __shfl_xor_sync(0xffffffffu, acc1.w, o);
    }

    if (eg == 0) {
        float rden = 1.0f / (den + 1e-16f);
        float* op = g_out1 + (size_t)n * 64 + c * 8;
        const float* bp = b1 + c * 8;
        float4 o0, o1;
        o0.x = fmaxf(acc0.x * rden + __ldg(bp + 0), 0.f);
        o0.y = fmaxf(acc0.y * rden + __ldg(bp + 1), 0.f);
        o0.z = fmaxf(acc0.z * rden + __ldg(bp + 2), 0.f);
        o0.w = fmaxf(acc0.w * rden + __ldg(bp + 3), 0.f);
        o1.x = fmaxf(acc1.x * rden + __ldg(bp + 4), 0.f);
        o1.y = fmaxf(acc1.y * rden + __ldg(bp + 5), 0.f);
        o1.z = fmaxf(acc1.z * rden + __ldg(bp + 6), 0.f);
        o1.w = fmaxf(acc1.w * rden + __ldg(bp + 7), 0.f);
        *(float4*)(op)     = o0;
        *(float4*)(op + 4) = o1;
    }
}

// ---------------- layer2 node phase: out1 @ W2, a2 ----------------------------
__global__ void k_l2(const float* __restrict__ W2,
                     const float* __restrict__ aS2, const float* __restrict__ aD2) {
    __shared__ float Wsm[64 * 40];
    __shared__ float aSs[40], aDs[40];
    int t = threadIdx.x;
    for (int i = t; i < 64 * 40; i += 128) Wsm[i] = W2[i];
    if (t < 40) { aSs[t] = aS2[t]; aDs[t] = aD2[t]; }
    __syncthreads();
    int n = blockIdx.x * 128 + t;
    if (n >= NN) return;
    float acc[40] = {};
    const float* r = g_out1 + (size_t)n * 64;
#pragma unroll
    for (int k4 = 0; k4 < 16; k4++) {
        float4 v = *(const float4*)(r + k4 * 4);
#pragma unroll
        for (int c = 0; c < 40; c++) {
            acc[c] += v.x * Wsm[(4 * k4 + 0) * 40 + c]
                    + v.y * Wsm[(4 * k4 + 1) * 40 + c]
                    + v.z * Wsm[(4 * k4 + 2) * 40 + c]
                    + v.w * Wsm[(4 * k4 + 3) * 40 + c];
        }
    }
    float s2 = 0.f, d2 = 0.f;
#pragma unroll
    for (int c = 0; c < 40; c++) {
        g_h2[(size_t)n * 40 + c] = acc[c];
        s2 += acc[c] * aSs[c];
        d2 += acc[c] * aDs[c];
    }
    g_as2[n] = s2;
    g_ad2[n] = d2;
}

// ---------------- layer2 aggregation: SINGLE PASS + bias + log_softmax --------
// lane = (edge-group 0..3) x (col-group 0..7); col-group c covers cols 5c..5c+4.
__global__ void k_agg2(const float* __restrict__ b2, float* __restrict__ out) {
    int n = (blockIdx.x * blockDim.x + threadIdx.x) >> 5;
    int lane = threadIdx.x & 31;
    if (n >= NN) return;
    int eg = lane >> 3;
    int c  = lane & 7;
    int beg = g_rowp[n], end = g_rowp[n + 1];
    float myad = g_ad2[n];

    float den = 0.f;
    float a[5] = {};
    for (int j = beg + eg; j < end; j += 4) {
        int s = g_esrc[j];
        float ex = lrelu_exp(g_as2[s] + myad);
        den += ex;
        const float* hr = g_h2 + (size_t)s * 40 + c * 5;
#pragma unroll
        for (int i = 0; i < 5; i++) a[i] += ex * hr[i];
    }
#pragma unroll
    for (int o = 8; o <= 16; o <<= 1) {
        den  += __shfl_xor_sync(0xffffffffu, den, o);
#pragma unroll
        for (int i = 0; i < 5; i++)
            a[i] += __shfl_xor_sync(0xffffffffu, a[i], o);
    }
    float rden = 1.0f / (den + 1e-16f);

    // v[i]: this lane's 5 logits (duplicated across the 4 edge groups)
    float v[5], m = -FLT_MAX;
#pragma unroll
    for (int i = 0; i < 5; i++) {
        v[i] = a[i] * rden + __ldg(b2 + c * 5 + i);
        m = fmaxf(m, v[i]);
    }
#pragma unroll
    for (int o = 16; o > 0; o >>= 1)
        m = fmaxf(m, __shfl_xor_sync(0xffffffffu, m, o));
    float sum = 0.f;
    if (eg == 0) {
#pragma unroll
        for (int i = 0; i < 5; i++) sum += __expf(v[i] - m);
    }
#pragma unroll
    for (int o = 16; o > 0; o >>= 1)
        sum += __shfl_xor_sync(0xffffffffu, sum, o);
    float ls = m + logf(sum);
    if (eg == 0) {
        float* op = out + (size_t)n * 40 + c * 5;
#pragma unroll
        for (int i = 0; i < 5; i++) op[i] = v[i] - ls;
    }
}

// ------------------------------------------------------------------------------
static cudaStream_t g_s1;
static cudaEvent_t g_evA, g_evB;
static bool g_init = false;

extern "C" void kernel_launch(void* const* d_in, const int* in_sizes, int n_in,
                              void* d_out, int out_size) {
    const float* x     = (const float*)d_in[0];
    const int*   ei    = (const int*)d_in[1];
    const float* W1    = (const float*)d_in[2];
    const float* attS1 = (const float*)d_in[3];
    const float* attD1 = (const float*)d_in[4];
    const float* b1    = (const float*)d_in[5];
    const float* W2    = (const float*)d_in[6];
    const float* attS2 = (const float*)d_in[7];
    const float* attD2 = (const float*)d_in[8];
    const float* b2    = (const float*)d_in[9];
    float* out = (float*)d_out;

    if (!g_init) {
        cudaStreamCreateWithFlags(&g_s1, cudaStreamNonBlocking);
        cudaEventCreateWithFlags(&g_evA, cudaEventDisableTiming);
        cudaEventCreateWithFlags(&g_evB, cudaEventDisableTiming);
        g_init = true;
    }

    int E = in_sizes[1] / 2;
    if (E > EMAX) E = EMAX;
    int ET = E + NN;

    // fork: CSR build on g_s1, GEMM1 on the main (null) stream
    cudaEventRecord(g_evA, 0);
    cudaStreamWaitEvent(g_s1, g_evA, 0);

    k_zdeg<<<(NN + 255) / 256, 256, 0, g_s1>>>();
    k_decode<<<(ET + 255) / 256, 256, 0, g_s1>>>(ei, E);
    k_scan<<<1, 1024, 0, g_s1>>>(ET);
    k_scatter<<<(ET + 255) / 256, 256, 0, g_s1>>>(ET);
    cudaEventRecord(g_evB, g_s1);

    k_gemm1<<<(NN + 63) / 64, 256>>>(x, W1, attS1, attD1);

    // join, then the dependent chain
    cudaStreamWaitEvent(0, g_evB, 0);
    k_agg1<<<(NN * 32 + 255) / 256, 256>>>(b1);
    k_l2<<<(NN + 127) / 128, 128>>>(W2, attS2, attD2);
    k_agg2<<<(NN * 32 + 255) / 256, 256>>>(b2, out);
}

// round 14
// speedup vs baseline: 1.8823x; 1.2780x over previous
#include <cuda_runtime.h>
#include <cstdint>
#include <cfloat>

#define NN 50000
#define FIN 512
#define H1C 64     // 8 heads * 8
#define H2C 40     // 1 head * 40
#define EMAX 1700000

// ---------------- scratch (device globals; no allocation allowed) -------------
__device__ int   g_esrc[EMAX + NN];   // src sorted by dst (CSR payload)
__device__ int   g_deg[NN];           // in-degree histogram
__device__ int   g_rowp[NN + 1];      // CSR row pointers
__device__ int   g_pos[NN];           // scatter cursors
__device__ float g_h1[NN * H1C];      // x @ W1
__device__ float g_as1[NN * 8];       // a_src layer1
__device__ float g_ad1[NN * 8];       // a_dst layer1
__device__ float g_out1[NN * H1C];    // relu(agg1 + b1)
__device__ float g_h2[NN * H2C];      // out1 @ W2
__device__ float g_as2[NN];
__device__ float g_ad2[NN];

__device__ __forceinline__ float lrelu_exp(float e) {
    e = (e < 0.f) ? 0.2f * e : e;
    return __expf(e);
}

__device__ __forceinline__ unsigned f2tf32(float f) {
    unsigned r;
    asm("cvt.rna.tf32.f32 %0, %1;" : "=r"(r) : "f"(f));
    return r;
}

__device__ __forceinline__ void mma_tf32(float* d, const unsigned* a, unsigned b0, unsigned b1) {
    asm volatile(
        "mma.sync.aligned.m16n8k8.row.col.f32.tf32.tf32.f32 "
        "{%0,%1,%2,%3}, {%4,%5,%6,%7}, {%8,%9}, {%0,%1,%2,%3};"
        : "+f"(d[0]), "+f"(d[1]), "+f"(d[2]), "+f"(d[3])
        : "r"(a[0]), "r"(a[1]), "r"(a[2]), "r"(a[3]), "r"(b0), "r"(b1));
}

// ---------------- CSR build ----------------------------------------------------
__global__ void k_zdeg() {
    int i = blockIdx.x * blockDim.x + threadIdx.x;
    if (i < NN) g_deg[i] = 0;
}

// histogram of dst (decode int32 OR int64 little-endian on the fly)
__global__ void k_decode(const int* __restrict__ w, int E) {
    bool is64 = (w[1] == 0 && w[3] == 0 && w[5] == 0 && w[7] == 0);
    int i = blockIdx.x * blockDim.x + threadIdx.x;
    int ET = E + NN;
    if (i >= ET) return;
    int d;
    if (i >= E) d = i - E;
    else if (is64) d = (int)((const long long*)w)[E + i];
    else d = w[E + i];
    atomicAdd(&g_deg[d], 1);
}

// single-block exclusive scan of g_deg -> g_rowp, g_pos
__global__ void k_scan(int ET) {
    __shared__ int sh[1024];
    int t = threadIdx.x;
    const int CH = (NN + 1023) / 1024;     // 49
    int b = t * CH;
    int e = b + CH; if (e > NN) e = NN; if (b > NN) b = NN;
    int s = 0;
    for (int i = b; i < e; i++) s += g_deg[i];
    sh[t] = s;
    __syncthreads();
    for (int off = 1; off < 1024; off <<= 1) {
        int v = (t >= off) ? sh[t - off] : 0;
        __syncthreads();
        sh[t] += v;
        __syncthreads();
    }
    int run = sh[t] - s;                   // exclusive prefix
    for (int i = b; i < e; i++) {
        int d = g_deg[i];
        g_rowp[i] = run;
        g_pos[i]  = run;
        run += d;
    }
    if (t == 1023) g_rowp[NN] = ET;
}

__global__ void k_scatter(const int* __restrict__ w, int E) {
    bool is64 = (w[1] == 0 && w[3] == 0 && w[5] == 0 && w[7] == 0);
    int i = blockIdx.x * blockDim.x + threadIdx.x;
    int ET = E + NN;
    if (i >= ET) return;
    int s, d;
    if (i >= E) { s = d = i - E; }
    else if (is64) {
        const long long* e64 = (const long long*)w;
        s = (int)e64[i]; d = (int)e64[E + i];
    } else {
        s = w[i]; d = w[E + i];
    }
    int p = atomicAdd(&g_pos[d], 1);
    g_esrc[p] = s;
}

// ---------------- GEMM1 (tf32 tensor cores): h1 = x @ W1, fused a1 ------------
// BM=256, BN=64, BK=16. 256 threads = 8 warps; warp owns 32 rows (2 m16 tiles),
// all 64 cols (8 n8 tiles = 8 heads). Strides 264/72 (== 8 mod 32) make all
// fragment LDS bank-conflict-free.
__global__ void k_gemm1(const float* __restrict__ x, const float* __restrict__ W,
                        const float* __restrict__ attS, const float* __restrict__ attD) {
    __shared__ unsigned As[16][264];   // [k][m] tf32
    __shared__ unsigned Bs[16][72];    // [k][n] tf32
    int t = threadIdx.x;
    int warp = t >> 5, lane = t & 31;
    int g = lane >> 2, q = lane & 3;
    int m0 = blockIdx.x * 256;

    float acc[2][8][4];
#pragma unroll
    for (int mt = 0; mt < 2; mt++)
#pragma unroll
        for (int n8 = 0; n8 < 8; n8++)
#pragma unroll
            for (int i = 0; i < 4; i++) acc[mt][n8][i] = 0.f;

    int lm = t >> 2;         // 0..63 (A-fill row within group)
    int lkq = t & 3;         // which float4 along k
    int bk = t >> 4;         // 0..15 (B-fill k row)
    int bn = t & 15;         // 0..15 (B-fill float4 along n)

    for (int k0 = 0; k0 < FIN; k0 += 16) {
        // fill A: 256 rows x 16 k
#pragma unroll
        for (int it = 0; it < 4; it++) {
            int m = lm + 64 * it;
            int gm = m0 + m;
            float4 v = make_float4(0.f, 0.f, 0.f, 0.f);
            if (gm < NN) v = *(const float4*)(x + (size_t)gm * FIN + k0 + 4 * lkq);
            As[4 * lkq + 0][m] = f2tf32(v.x);
            As[4 * lkq + 1][m] = f2tf32(v.y);
            As[4 * lkq + 2][m] = f2tf32(v.z);
            As[4 * lkq + 3][m] = f2tf32(v.w);
        }
        // fill B: 16 k x 64 n
        {
            float4 v = *(const float4*)(W + (size_t)(k0 + bk) * 64 + 4 * bn);
            Bs[bk][4 * bn + 0] = f2tf32(v.x);
            Bs[bk][4 * bn + 1] = f2tf32(v.y);
            Bs[bk][4 * bn + 2] = f2tf32(v.z);
            Bs[bk][4 * bn + 3] = f2tf32(v.w);
        }
        __syncthreads();

#pragma unroll
        for (int kk = 0; kk < 16; kk += 8) {
            unsigned a[2][4];
#pragma unroll
            for (int mt = 0; mt < 2; mt++) {
                int r = warp * 32 + 16 * mt + g;
                a[mt][0] = As[kk + q][r];
                a[mt][1] = As[kk + q][r + 8];
                a[mt][2] = As[kk + q + 4][r];
                a[mt][3] = As[kk + q + 4][r + 8];
            }
#pragma unroll
            for (int n8 = 0; n8 < 8; n8++) {
                unsigned b0 = Bs[kk + q][8 * n8 + g];
                unsigned b1 = Bs[kk + q + 4][8 * n8 + g];
                mma_tf32(acc[0][n8], a[0], b0, b1);
                mma_tf32(acc[1][n8], a[1], b0, b1);
            }
        }
        __syncthreads();
    }

    // epilogue: store h1 + fused per-head attention dots (n8 == head)
#pragma unroll
    for (int mt = 0; mt < 2; mt++) {
        int rlo = m0 + warp * 32 + 16 * mt + g;
        int rhi = rlo + 8;
        float sLo = 0.f, dLo = 0.f, sHi = 0.f, dHi = 0.f;  // per-head below
#pragma unroll
        for (int n8 = 0; n8 < 8; n8++) {
            float c0 = acc[mt][n8][0], c1 = acc[mt][n8][1];
            float c2 = acc[mt][n8][2], c3 = acc[mt][n8][3];
            int col = 8 * n8 + 2 * q;
            if (rlo < NN) { float2 v; v.x = c0; v.y = c1; *(float2*)(g_h1 + (size_t)rlo * 64 + col) = v; }
            if (rhi < NN) { float2 v; v.x = c2; v.y = c3; *(float2*)(g_h1 + (size_t)rhi * 64 + col) = v; }
            float aS0 = __ldg(attS + col), aS1 = __ldg(attS + col + 1);
            float aD0 = __ldg(attD + col), aD1 = __ldg(attD + col + 1);
            sLo = c0 * aS0 + c1 * aS1;
            dLo = c0 * aD0 + c1 * aD1;
            sHi = c2 * aS0 + c3 * aS1;
            dHi = c2 * aD0 + c3 * aD1;
            // reduce over the quad (q = 0..3 covers the 8 cols of head n8)
#pragma unroll
            for (int o = 1; o <= 2; o <<= 1) {
                sLo += __shfl_xor_sync(0xffffffffu, sLo, o);
                dLo += __shfl_xor_sync(0xffffffffu, dLo, o);
                sHi += __shfl_xor_sync(0xffffffffu, sHi, o);
                dHi += __shfl_xor_sync(0xffffffffu, dHi, o);
            }
            if (q == 0) {
                if (rlo < NN) { g_as1[rlo * 8 + n8] = sLo; g_ad1[rlo * 8 + n8] = dLo; }
                if (rhi < NN) { g_as1[rhi * 8 + n8] = sHi; g_ad1[rhi * 8 + n8] = dHi; }
            }
        }
    }
}

// ---------------- layer1 aggregation: SINGLE PASS, warp per dst node ----------
__global__ void k_agg1(const float* __restrict__ b1) {
    int n = (blockIdx.x * blockDim.x + threadIdx.x) >> 5;
    int lane = threadIdx.x & 31;
    if (n >= NN) return;
    int eg = lane >> 3;       // 0..3
    int c  = lane & 7;        // col group == head
    int beg = g_rowp[n], end = g_rowp[n + 1];

    float myad = g_ad1[n * 8 + c];
    float den = 0.f;
    float4 acc0 = make_float4(0.f, 0.f, 0.f, 0.f);
    float4 acc1 = make_float4(0.f, 0.f, 0.f, 0.f);

    for (int j = beg + eg; j < end; j += 4) {
        int s = g_esrc[j];
        float ex = lrelu_exp(g_as1[s * 8 + c] + myad);
        const float* hr = g_h1 + (size_t)s * 64 + c * 8;
        float4 h0 = *(const float4*)(hr);
        float4 h1v = *(const float4*)(hr + 4);
        den += ex;
        acc0.x += ex * h0.x;  acc0.y += ex * h0.y;  acc0.z += ex * h0.z;  acc0.w += ex * h0.w;
        acc1.x += ex * h1v.x; acc1.y += ex * h1v.y; acc1.z += ex * h1v.z; acc1.w += ex * h1v.w;
    }

#pragma unroll
    for (int o = 8; o <= 16; o <<= 1) {
        den    += __shfl_xor_sync(0xffffffffu, den, o);
        acc0.x += __shfl_xor_sync(0xffffffffu, acc0.x, o);
        acc0.y += __shfl_xor_sync(0xffffffffu, acc0.y, o);
        acc0.z += __shfl_xor_sync(0xffffffffu, acc0.z, o);
        acc0.w += __shfl_xor_sync(0xffffffffu, acc0.w, o);
        acc1.x += __shfl_xor_sync(0xffffffffu, acc1.x, o);
        acc1.y += __shfl_xor_sync(0xffffffffu, acc1.y, o);
        acc1.z += __shfl_xor_sync(0xffffffffu, acc1.z, o);
        acc1.w += __shfl_xor_sync(0xffffffffu, acc1.w, o);
    }

    if (eg == 0) {
        float rden = 1.0f / (den + 1e-16f);
        float* op = g_out1 + (size_t)n * 64 + c * 8;
        const float* bp = b1 + c * 8;
        float4 o0, o1;
        o0.x = fmaxf(acc0.x * rden + __ldg(bp + 0), 0.f);
        o0.y = fmaxf(acc0.y * rden + __ldg(bp + 1), 0.f);
        o0.z = fmaxf(acc0.z * rden + __ldg(bp + 2), 0.f);
        o0.w = fmaxf(acc0.w * rden + __ldg(bp + 3), 0.f);
        o1.x = fmaxf(acc1.x * rden + __ldg(bp + 4), 0.f);
        o1.y = fmaxf(acc1.y * rden + __ldg(bp + 5), 0.f);
        o1.z = fmaxf(acc1.z * rden + __ldg(bp + 6), 0.f);
        o1.w = fmaxf(acc1.w * rden + __ldg(bp + 7), 0.f);
        *(float4*)(op)     = o0;
        *(float4*)(op + 4) = o1;
    }
}

// ---------------- layer2 node phase: out1 @ W2, a2 ----------------------------
__global__ void k_l2(const float* __restrict__ W2,
                     const float* __restrict__ aS2, const float* __restrict__ aD2) {
    __shared__ float Wsm[64 * 40];
    __shared__ float aSs[40], aDs[40];
    int t = threadIdx.x;
    for (int i = t; i < 64 * 40; i += 128) Wsm[i] = W2[i];
    if (t < 40) { aSs[t] = aS2[t]; aDs[t] = aD2[t]; }
    __syncthreads();
    int n = blockIdx.x * 128 + t;
    if (n >= NN) return;
    float acc[40] = {};
    const float* r = g_out1 + (size_t)n * 64;
#pragma unroll
    for (int k4 = 0; k4 < 16; k4++) {
        float4 v = *(const float4*)(r + k4 * 4);
#pragma unroll
        for (int c = 0; c < 40; c++) {
            acc[c] += v.x * Wsm[(4 * k4 + 0) * 40 + c]
                    + v.y * Wsm[(4 * k4 + 1) * 40 + c]
                    + v.z * Wsm[(4 * k4 + 2) * 40 + c]
                    + v.w * Wsm[(4 * k4 + 3) * 40 + c];
        }
    }
    float s2 = 0.f, d2 = 0.f;
#pragma unroll
    for (int c = 0; c < 40; c++) {
        g_h2[(size_t)n * 40 + c] = acc[c];
        s2 += acc[c] * aSs[c];
        d2 += acc[c] * aDs[c];
    }
    g_as2[n] = s2;
    g_ad2[n] = d2;
}

// ---------------- layer2 aggregation: SINGLE PASS + bias + log_softmax --------
__global__ void k_agg2(const float* __restrict__ b2, float* __restrict__ out) {
    int n = (blockIdx.x * blockDim.x + threadIdx.x) >> 5;
    int lane = threadIdx.x & 31;
    if (n >= NN) return;
    int eg = lane >> 3;
    int c  = lane & 7;
    int beg = g_rowp[n], end = g_rowp[n + 1];
    float myad = g_ad2[n];

    float den = 0.f;
    float a[5] = {};
    for (int j = beg + eg; j < end; j += 4) {
        int s = g_esrc[j];
        float ex = lrelu_exp(g_as2[s] + myad);
        den += ex;
        const float* hr = g_h2 + (size_t)s * 40 + c * 5;
#pragma unroll
        for (int i = 0; i < 5; i++) a[i] += ex * hr[i];
    }
#pragma unroll
    for (int o = 8; o <= 16; o <<= 1) {
        den  += __shfl_xor_sync(0xffffffffu, den, o);
#pragma unroll
        for (int i = 0; i < 5; i++)
            a[i] += __shfl_xor_sync(0xffffffffu, a[i], o);
    }
    float rden = 1.0f / (den + 1e-16f);

    float v[5], m = -FLT_MAX;
#pragma unroll
    for (int i = 0; i < 5; i++) {
        v[i] = a[i] * rden + __ldg(b2 + c * 5 + i);
        m = fmaxf(m, v[i]);
    }
#pragma unroll
    for (int o = 16; o > 0; o >>= 1)
        m = fmaxf(m, __shfl_xor_sync(0xffffffffu, m, o));
    float sum = 0.f;
    if (eg == 0) {
#pragma unroll
        for (int i = 0; i < 5; i++) sum += __expf(v[i] - m);
    }
#pragma unroll
    for (int o = 16; o > 0; o >>= 1)
        sum += __shfl_xor_sync(0xffffffffu, sum, o);
    float ls = m + logf(sum);
    if (eg == 0) {
        float* op = out + (size_t)n * 40 + c * 5;
#pragma unroll
        for (int i = 0; i < 5; i++) op[i] = v[i] - ls;
    }
}

// ------------------------------------------------------------------------------
static cudaStream_t g_s1;
static cudaEvent_t g_evA, g_evB;
static bool g_init = false;

extern "C" void kernel_launch(void* const* d_in, const int* in_sizes, int n_in,
                              void* d_out, int out_size) {
    const float* x     = (const float*)d_in[0];
    const int*   ei    = (const int*)d_in[1];
    const float* W1    = (const float*)d_in[2];
    const float* attS1 = (const float*)d_in[3];
    const float* attD1 = (const float*)d_in[4];
    const float* b1    = (const float*)d_in[5];
    const float* W2    = (const float*)d_in[6];
    const float* attS2 = (const float*)d_in[7];
    const float* attD2 = (const float*)d_in[8];
    const float* b2    = (const float*)d_in[9];
    float* out = (float*)d_out;

    if (!g_init) {
        cudaStreamCreateWithFlags(&g_s1, cudaStreamNonBlocking);
        cudaEventCreateWithFlags(&g_evA, cudaEventDisableTiming);
        cudaEventCreateWithFlags(&g_evB, cudaEventDisableTiming);
        g_init = true;
    }

    int E = in_sizes[1] / 2;
    if (E > EMAX) E = EMAX;
    int ET = E + NN;

    // fork: CSR build on g_s1, GEMM1 on the main (null) stream
    cudaEventRecord(g_evA, 0);
    cudaStreamWaitEvent(g_s1, g_evA, 0);

    k_zdeg<<<(NN + 255) / 256, 256, 0, g_s1>>>();
    k_decode<<<(ET + 255) / 256, 256, 0, g_s1>>>(ei, E);
    k_scan<<<1, 1024, 0, g_s1>>>(ET);
    k_scatter<<<(ET + 255) / 256, 256, 0, g_s1>>>(ei, E);
    cudaEventRecord(g_evB, g_s1);

    k_gemm1<<<(NN + 255) / 256, 256>>>(x, W1, attS1, attD1);

    // join, then the dependent chain
    cudaStreamWaitEvent(0, g_evB, 0);
    k_agg1<<<(NN * 32 + 255) / 256, 256>>>(b1);
    k_l2<<<(NN + 127) / 128, 128>>>(W2, attS2, attD2);
    k_agg2<<<(NN * 32 + 255) / 256, 256>>>(b2, out);
}

// round 15
// speedup vs baseline: 2.1043x; 1.1180x over previous
#include <cuda_runtime.h>
#include <cuda_fp16.h>
#include <cstdint>
#include <cfloat>

#define NN 50000
#define FIN 512
#define H1C 64     // 8 heads * 8
#define H2C 40     // 1 head * 40
#define EMAX 1700000

// ---------------- scratch (device globals; no allocation allowed) -------------
__device__ int    g_esrc[EMAX + NN];   // src sorted by dst (CSR payload)
__device__ int    g_deg[NN];           // in-degree histogram
__device__ int    g_rowp[NN + 1];      // CSR row pointers
__device__ int    g_pos[NN];           // scatter cursors
__device__ __half g_h1h[NN * H1C];     // x @ W1 (fp16 messages)
__device__ float  g_as1[NN * 8];       // a_src layer1 (fp32)
__device__ float  g_ad1[NN * 8];       // a_dst layer1 (fp32)
__device__ float  g_out1[NN * H1C];    // relu(agg1 + b1), fp32
__device__ __half g_h2h[NN * H2C];     // out1 @ W2 (fp16 messages)
__device__ float  g_as2[NN];
__device__ float  g_ad2[NN];

__device__ __forceinline__ float lrelu_exp(float e) {
    e = (e < 0.f) ? 0.2f * e : e;
    return __expf(e);
}

__device__ __forceinline__ unsigned f2tf32(float f) {
    unsigned r;
    asm("cvt.rna.tf32.f32 %0, %1;" : "=r"(r) : "f"(f));
    return r;
}

__device__ __forceinline__ void mma_tf32(float* d, const unsigned* a, unsigned b0, unsigned b1) {
    asm volatile(
        "mma.sync.aligned.m16n8k8.row.col.f32.tf32.tf32.f32 "
        "{%0,%1,%2,%3}, {%4,%5,%6,%7}, {%8,%9}, {%0,%1,%2,%3};"
        : "+f"(d[0]), "+f"(d[1]), "+f"(d[2]), "+f"(d[3])
        : "r"(a[0]), "r"(a[1]), "r"(a[2]), "r"(a[3]), "r"(b0), "r"(b1));
}

// ---------------- CSR build ----------------------------------------------------
__global__ void k_zdeg() {
    int i = blockIdx.x * blockDim.x + threadIdx.x;
    if (i < NN) g_deg[i] = 0;
}

// histogram of dst; 4 edges per thread for MLP
__global__ void k_decode(const int* __restrict__ w, int E) {
    bool is64 = (w[1] == 0 && w[3] == 0 && w[5] == 0 && w[7] == 0);
    int i4 = (blockIdx.x * blockDim.x + threadIdx.x) * 4;
    int ET = E + NN;
    if (i4 >= ET) return;
    if (i4 + 3 < E) {
        int d0, d1, d2, d3;
        if (is64) {
            const long long* p = (const long long*)w + E + i4;
            longlong2 a = *(const longlong2*)(p);
            longlong2 b = *(const longlong2*)(p + 2);
            d0 = (int)a.x; d1 = (int)a.y; d2 = (int)b.x; d3 = (int)b.y;
        } else {
            int4 v = *(const int4*)(w + E + i4);
            d0 = v.x; d1 = v.y; d2 = v.z; d3 = v.w;
        }
        atomicAdd(&g_deg[d0], 1);
        atomicAdd(&g_deg[d1], 1);
        atomicAdd(&g_deg[d2], 1);
        atomicAdd(&g_deg[d3], 1);
    } else {
        for (int i = i4; i < i4 + 4 && i < ET; i++) {
            int d;
            if (i >= E) d = i - E;
            else if (is64) d = (int)((const long long*)w)[E + i];
            else d = w[E + i];
            atomicAdd(&g_deg[d], 1);
        }
    }
}

// single-block exclusive scan of g_deg -> g_rowp, g_pos
__global__ void k_scan(int ET) {
    __shared__ int sh[1024];
    int t = threadIdx.x;
    const int CH = (NN + 1023) / 1024;     // 49
    int b = t * CH;
    int e = b + CH; if (e > NN) e = NN; if (b > NN) b = NN;
    int s = 0;
    for (int i = b; i < e; i++) s += g_deg[i];
    sh[t] = s;
    __syncthreads();
    for (int off = 1; off < 1024; off <<= 1) {
        int v = (t >= off) ? sh[t - off] : 0;
        __syncthreads();
        sh[t] += v;
        __syncthreads();
    }
    int run = sh[t] - s;                   // exclusive prefix
    for (int i = b; i < e; i++) {
        int d = g_deg[i];
        g_rowp[i] = run;
        g_pos[i]  = run;
        run += d;
    }
    if (t == 1023) g_rowp[NN] = ET;
}

// scatter src into CSR slots; 4 edges per thread
__global__ void k_scatter(const int* __restrict__ w, int E) {
    bool is64 = (w[1] == 0 && w[3] == 0 && w[5] == 0 && w[7] == 0);
    int i4 = (blockIdx.x * blockDim.x + threadIdx.x) * 4;
    int ET = E + NN;
    if (i4 >= ET) return;
    if (i4 + 3 < E) {
        int s0, s1, s2, s3, d0, d1, d2, d3;
        if (is64) {
            const long long* ps = (const long long*)w + i4;
            const long long* pd = (const long long*)w + E + i4;
            longlong2 sa = *(const longlong2*)(ps);
            longlong2 sb = *(const longlong2*)(ps + 2);
            longlong2 da = *(const longlong2*)(pd);
            longlong2 db = *(const longlong2*)(pd + 2);
            s0 = (int)sa.x; s1 = (int)sa.y; s2 = (int)sb.x; s3 = (int)sb.y;
            d0 = (int)da.x; d1 = (int)da.y; d2 = (int)db.x; d3 = (int)db.y;
        } else {
            int4 sv = *(const int4*)(w + i4);
            int4 dv = *(const int4*)(w + E + i4);
            s0 = sv.x; s1 = sv.y; s2 = sv.z; s3 = sv.w;
            d0 = dv.x; d1 = dv.y; d2 = dv.z; d3 = dv.w;
        }
        int p0 = atomicAdd(&g_pos[d0], 1);
        int p1 = atomicAdd(&g_pos[d1], 1);
        int p2 = atomicAdd(&g_pos[d2], 1);
        int p3 = atomicAdd(&g_pos[d3], 1);
        g_esrc[p0] = s0; g_esrc[p1] = s1; g_esrc[p2] = s2; g_esrc[p3] = s3;
    } else {
        for (int i = i4; i < i4 + 4 && i < ET; i++) {
            int s, d;
            if (i >= E) { s = d = i - E; }
            else if (is64) {
                const long long* e64 = (const long long*)w;
                s = (int)e64[i]; d = (int)e64[E + i];
            } else {
                s = w[i]; d = w[E + i];
            }
            int p = atomicAdd(&g_pos[d], 1);
            g_esrc[p] = s;
        }
    }
}

// ---------------- GEMM1 (tf32 tensor cores): h1 = x @ W1, fused a1 ------------
// BM=256, BN=64, BK=16. h1 stored fp16; a1 dots computed in fp32 pre-rounding.
__global__ void k_gemm1(const float* __restrict__ x, const float* __restrict__ W,
                        const float* __restrict__ attS, const float* __restrict__ attD) {
    __shared__ unsigned As[16][264];   // [k][m] tf32
    __shared__ unsigned Bs[16][72];    // [k][n] tf32
    int t = threadIdx.x;
    int warp = t >> 5, lane = t & 31;
    int g = lane >> 2, q = lane & 3;
    int m0 = blockIdx.x * 256;

    float acc[2][8][4];
#pragma unroll
    for (int mt = 0; mt < 2; mt++)
#pragma unroll
        for (int n8 = 0; n8 < 8; n8++)
#pragma unroll
            for (int i = 0; i < 4; i++) acc[mt][n8][i] = 0.f;

    int lm = t >> 2;
    int lkq = t & 3;
    int bk = t >> 4;
    int bn = t & 15;

    for (int k0 = 0; k0 < FIN; k0 += 16) {
#pragma unroll
        for (int it = 0; it < 4; it++) {
            int m = lm + 64 * it;
            int gm = m0 + m;
            float4 v = make_float4(0.f, 0.f, 0.f, 0.f);
            if (gm < NN) v = *(const float4*)(x + (size_t)gm * FIN + k0 + 4 * lkq);
            As[4 * lkq + 0][m] = f2tf32(v.x);
            As[4 * lkq + 1][m] = f2tf32(v.y);
            As[4 * lkq + 2][m] = f2tf32(v.z);
            As[4 * lkq + 3][m] = f2tf32(v.w);
        }
        {
            float4 v = *(const float4*)(W + (size_t)(k0 + bk) * 64 + 4 * bn);
            Bs[bk][4 * bn + 0] = f2tf32(v.x);
            Bs[bk][4 * bn + 1] = f2tf32(v.y);
            Bs[bk][4 * bn + 2] = f2tf32(v.z);
            Bs[bk][4 * bn + 3] = f2tf32(v.w);
        }
        __syncthreads();

#pragma unroll
        for (int kk = 0; kk < 16; kk += 8) {
            unsigned a[2][4];
#pragma unroll
            for (int mt = 0; mt < 2; mt++) {
                int r = warp * 32 + 16 * mt + g;
                a[mt][0] = As[kk + q][r];
                a[mt][1] = As[kk + q][r + 8];
                a[mt][2] = As[kk + q + 4][r];
                a[mt][3] = As[kk + q + 4][r + 8];
            }
#pragma unroll
            for (int n8 = 0; n8 < 8; n8++) {
                unsigned b0 = Bs[kk + q][8 * n8 + g];
                unsigned b1 = Bs[kk + q + 4][8 * n8 + g];
                mma_tf32(acc[0][n8], a[0], b0, b1);
                mma_tf32(acc[1][n8], a[1], b0, b1);
            }
        }
        __syncthreads();
    }

#pragma unroll
    for (int mt = 0; mt < 2; mt++) {
        int rlo = m0 + warp * 32 + 16 * mt + g;
        int rhi = rlo + 8;
#pragma unroll
        for (int n8 = 0; n8 < 8; n8++) {
            float c0 = acc[mt][n8][0], c1 = acc[mt][n8][1];
            float c2 = acc[mt][n8][2], c3 = acc[mt][n8][3];
            int col = 8 * n8 + 2 * q;
            if (rlo < NN) *(__half2*)(g_h1h + (size_t)rlo * 64 + col) = __floats2half2_rn(c0, c1);
            if (rhi < NN) *(__half2*)(g_h1h + (size_t)rhi * 64 + col) = __floats2half2_rn(c2, c3);
            float aS0 = __ldg(attS + col), aS1 = __ldg(attS + col + 1);
            float aD0 = __ldg(attD + col), aD1 = __ldg(attD + col + 1);
            float sLo = c0 * aS0 + c1 * aS1;
            float dLo = c0 * aD0 + c1 * aD1;
            float sHi = c2 * aS0 + c3 * aS1;
            float dHi = c2 * aD0 + c3 * aD1;
#pragma unroll
            for (int o = 1; o <= 2; o <<= 1) {
                sLo += __shfl_xor_sync(0xffffffffu, sLo, o);
                dLo += __shfl_xor_sync(0xffffffffu, dLo, o);
                sHi += __shfl_xor_sync(0xffffffffu, sHi, o);
                dHi += __shfl_xor_sync(0xffffffffu, dHi, o);
            }
            if (q == 0) {
                if (rlo < NN) { g_as1[rlo * 8 + n8] = sLo; g_ad1[rlo * 8 + n8] = dLo; }
                if (rhi < NN) { g_as1[rhi * 8 + n8] = sHi; g_ad1[rhi * 8 + n8] = dHi; }
            }
        }
    }
}

// ---------------- layer1 aggregation: SINGLE PASS, warp per dst node ----------
// lane = (edge-group eg 0..3) x (head c 0..7); h1 fp16 (16B per lane per edge).
__global__ void k_agg1(const float* __restrict__ b1) {
    int n = (blockIdx.x * blockDim.x + threadIdx.x) >> 5;
    int lane = threadIdx.x & 31;
    if (n >= NN) return;
    int eg = lane >> 3;
    int c  = lane & 7;
    int beg = g_rowp[n], end = g_rowp[n + 1];

    float myad = g_ad1[n * 8 + c];
    float den = 0.f;
    float a[8] = {};

    for (int j = beg + eg; j < end; j += 4) {
        int s = g_esrc[j];
        float ex = lrelu_exp(g_as1[s * 8 + c] + myad);
        uint4 u = *(const uint4*)(g_h1h + (size_t)s * 64 + c * 8);  // 8 halves
        float2 f0 = __half22float2(*(const __half2*)&u.x);
        float2 f1 = __half22float2(*(const __half2*)&u.y);
        float2 f2 = __half22float2(*(const __half2*)&u.z);
        float2 f3 = __half22float2(*(const __half2*)&u.w);
        den += ex;
        a[0] += ex * f0.x; a[1] += ex * f0.y;
        a[2] += ex * f1.x; a[3] += ex * f1.y;
        a[4] += ex * f2.x; a[5] += ex * f2.y;
        a[6] += ex * f3.x; a[7] += ex * f3.y;
    }

#pragma unroll
    for (int o = 8; o <= 16; o <<= 1) {
        den += __shfl_xor_sync(0xffffffffu, den, o);
#pragma unroll
        for (int i = 0; i < 8; i++)
            a[i] += __shfl_xor_sync(0xffffffffu, a[i], o);
    }

    if (eg == 0) {
        float rden = 1.0f / (den + 1e-16f);
        float* op = g_out1 + (size_t)n * 64 + c * 8;
        const float* bp = b1 + c * 8;
        float4 o0, o1;
        o0.x = fmaxf(a[0] * rden + __ldg(bp + 0), 0.f);
        o0.y = fmaxf(a[1] * rden + __ldg(bp + 1), 0.f);
        o0.z = fmaxf(a[2] * rden + __ldg(bp + 2), 0.f);
        o0.w = fmaxf(a[3] * rden + __ldg(bp + 3), 0.f);
        o1.x = fmaxf(a[4] * rden + __ldg(bp + 4), 0.f);
        o1.y = fmaxf(a[5] * rden + __ldg(bp + 5), 0.f);
        o1.z = fmaxf(a[6] * rden + __ldg(bp + 6), 0.f);
        o1.w = fmaxf(a[7] * rden + __ldg(bp + 7), 0.f);
        *(float4*)(op)     = o0;
        *(float4*)(op + 4) = o1;
    }
}

// ---------------- layer2 node phase: out1 @ W2, a2 ----------------------------
__global__ void k_l2(const float* __restrict__ W2,
                     const float* __restrict__ aS2, const float* __restrict__ aD2) {
    __shared__ float Wsm[64 * 40];
    __shared__ float aSs[40], aDs[40];
    int t = threadIdx.x;
    for (int i = t; i < 64 * 40; i += 128) Wsm[i] = W2[i];
    if (t < 40) { aSs[t] = aS2[t]; aDs[t] = aD2[t]; }
    __syncthreads();
    int n = blockIdx.x * 128 + t;
    if (n >= NN) return;
    float acc[40] = {};
    const float* r = g_out1 + (size_t)n * 64;
#pragma unroll
    for (int k4 = 0; k4 < 16; k4++) {
        float4 v = *(const float4*)(r + k4 * 4);
#pragma unroll
        for (int c = 0; c < 40; c++) {
            acc[c] += v.x * Wsm[(4 * k4 + 0) * 40 + c]
                    + v.y * Wsm[(4 * k4 + 1) * 40 + c]
                    + v.z * Wsm[(4 * k4 + 2) * 40 + c]
                    + v.w * Wsm[(4 * k4 + 3) * 40 + c];
        }
    }
    float s2 = 0.f, d2 = 0.f;
    __half2* hp = (__half2*)(g_h2h + (size_t)n * 40);
#pragma unroll
    for (int c = 0; c < 20; c++) {
        hp[c] = __floats2half2_rn(acc[2 * c], acc[2 * c + 1]);
        s2 += acc[2 * c] * aSs[2 * c] + acc[2 * c + 1] * aSs[2 * c + 1];
        d2 += acc[2 * c] * aDs[2 * c] + acc[2 * c + 1] * aDs[2 * c + 1];
    }
    g_as2[n] = s2;
    g_ad2[n] = d2;
}

// ---------------- layer2 aggregation: SINGLE PASS + bias + log_softmax --------
// lane = (eg 0..3) x (c 0..7). Lane c handles half2 cols {c, c+8} and, if c<4,
// {c+16} of the 20-half2 (40-col) row.
__global__ void k_agg2(const float* __restrict__ b2, float* __restrict__ out) {
    int n = (blockIdx.x * blockDim.x + threadIdx.x) >> 5;
    int lane = threadIdx.x & 31;
    if (n >= NN) return;
    int eg = lane >> 3;
    int c  = lane & 7;
    int beg = g_rowp[n], end = g_rowp[n + 1];
    float myad = g_ad2[n];

    float den = 0.f;
    float a0 = 0.f, a1 = 0.f, a2 = 0.f, a3 = 0.f, a4 = 0.f, a5 = 0.f;
    for (int j = beg + eg; j < end; j += 4) {
        int s = g_esrc[j];
        float ex = lrelu_exp(g_as2[s] + myad);
        den += ex;
        const __half2* hp = (const __half2*)(g_h2h + (size_t)s * 40);
        float2 f0 = __half22float2(hp[c]);
        float2 f1 = __half22float2(hp[c + 8]);
        a0 += ex * f0.x; a1 += ex * f0.y;
        a2 += ex * f1.x; a3 += ex * f1.y;
        if (c < 4) {
            float2 f2 = __half22float2(hp[c + 16]);
            a4 += ex * f2.x; a5 += ex * f2.y;
        }
    }
#pragma unroll
    for (int o = 8; o <= 16; o <<= 1) {
        den += __shfl_xor_sync(0xffffffffu, den, o);
        a0  += __shfl_xor_sync(0xffffffffu, a0, o);
        a1  += __shfl_xor_sync(0xffffffffu, a1, o);
        a2  += __shfl_xor_sync(0xffffffffu, a2, o);
        a3  += __shfl_xor_sync(0xffffffffu, a3, o);
        a4  += __shfl_xor_sync(0xffffffffu, a4, o);
        a5  += __shfl_xor_sync(0xffffffffu, a5, o);
    }
    float rden = 1.0f / (den + 1e-16f);

    // lane c logits: cols {2c,2c+1}, {2c+16,2c+17}, c<4: {2c+32,2c+33}
    float v0 = a0 * rden + __ldg(b2 + 2 * c);
    float v1 = a1 * rden + __ldg(b2 + 2 * c + 1);
    float v2 = a2 * rden + __ldg(b2 + 2 * c + 16);
    float v3 = a3 * rden + __ldg(b2 + 2 * c + 17);
    float v4 = -FLT_MAX, v5 = -FLT_MAX;
    if (c < 4) {
        v4 = a4 * rden + __ldg(b2 + 2 * c + 32);
        v5 = a5 * rden + __ldg(b2 + 2 * c + 33);
    }
    float m = fmaxf(fmaxf(fmaxf(v0, v1), fmaxf(v2, v3)), fmaxf(v4, v5));
#pragma unroll
    for (int o = 16; o > 0; o >>= 1)
        m = fmaxf(m, __shfl_xor_sync(0xffffffffu, m, o));
    float sum = 0.f;
    if (eg == 0) {
        sum = __expf(v0 - m) + __expf(v1 - m) + __expf(v2 - m) + __expf(v3 - m);
        if (c < 4) sum += __expf(v4 - m) + __expf(v5 - m);
    }
#pragma unroll
    for (int o = 16; o > 0; o >>= 1)
        sum += __shfl_xor_sync(0xffffffffu, sum, o);
    float ls = m + logf(sum);
    if (eg == 0) {
        float* op = out + (size_t)n * 40;
        float2 w0; w0.x = v0 - ls; w0.y = v1 - ls;
        float2 w1; w1.x = v2 - ls; w1.y = v3 - ls;
        *(float2*)(op + 2 * c)      = w0;
        *(float2*)(op + 2 * c + 16) = w1;
        if (c < 4) {
            float2 w2; w2.x = v4 - ls; w2.y = v5 - ls;
            *(float2*)(op + 2 * c + 32) = w2;
        }
    }
}

// ------------------------------------------------------------------------------
static cudaStream_t g_s1;
static cudaEvent_t g_evA, g_evB;
static bool g_init = false;

extern "C" void kernel_launch(void* const* d_in, const int* in_sizes, int n_in,
                              void* d_out, int out_size) {
    const float* x     = (const float*)d_in[0];
    const int*   ei    = (const int*)d_in[1];
    const float* W1    = (const float*)d_in[2];
    const float* attS1 = (const float*)d_in[3];
    const float* attD1 = (const float*)d_in[4];
    const float* b1    = (const float*)d_in[5];
    const float* W2    = (const float*)d_in[6];
    const float* attS2 = (const float*)d_in[7];
    const float* attD2 = (const float*)d_in[8];
    const float* b2    = (const float*)d_in[9];
    float* out = (float*)d_out;

    if (!g_init) {
        cudaStreamCreateWithFlags(&g_s1, cudaStreamNonBlocking);
        cudaEventCreateWithFlags(&g_evA, cudaEventDisableTiming);
        cudaEventCreateWithFlags(&g_evB, cudaEventDisableTiming);
        g_init = true;
    }

    int E = in_sizes[1] / 2;
    if (E > EMAX) E = EMAX;
    int ET = E + NN;

    // fork: CSR build on g_s1, GEMM1 on the main (null) stream
    cudaEventRecord(g_evA, 0);
    cudaStreamWaitEvent(g_s1, g_evA, 0);

    k_zdeg<<<(NN + 255) / 256, 256, 0, g_s1>>>();
    {
        int thr = (ET + 3) / 4;
        k_decode<<<(thr + 255) / 256, 256, 0, g_s1>>>(ei, E);
    }
    k_scan<<<1, 1024, 0, g_s1>>>(ET);
    {
        int thr = (ET + 3) / 4;
        k_scatter<<<(thr + 255) / 256, 256, 0, g_s1>>>(ei, E);
    }
    cudaEventRecord(g_evB, g_s1);

    k_gemm1<<<(NN + 255) / 256, 256>>>(x, W1, attS1, attD1);

    // join, then the dependent chain
    cudaStreamWaitEvent(0, g_evB, 0);
    k_agg1<<<(NN * 32 + 255) / 256, 256>>>(b1);
    k_l2<<<(NN + 127) / 128, 128>>>(W2, attS2, attD2);
    k_agg2<<<(NN * 32 + 255) / 256, 256>>>(b2, out);
}